// round 5
// baseline (speedup 1.0000x reference)
#include <cuda_runtime.h>
#include <math.h>

#define S0 3600
#define S1 720
#define S2 144
#define S3 36
#define S4 9

// ---------------- static device scratch (no runtime allocation) ----------------
__device__ __align__(16) float    g_x  [S0*S0];          // dense scattered input grid (51.8MB)
__device__ __align__(16) unsigned g_p1e[S1*S1*10];       // encoded max-pool accumulators (level1)
__device__ __align__(16) float    g_p1v[S1*S1*10];       // decoded values (0 at inactive)
__device__ __align__(16) int      g_list[S1*S1];         // active cell list at level1
__device__ int      g_cnt;
__device__ __align__(16) unsigned g_p2e[S2*S2*64];
__device__ __align__(16) float    g_p2v[S2*S2*64];
__device__ __align__(16) unsigned g_p3e[S3*S3*128];
__device__ __align__(16) float    g_p3v[S3*S3*128];
__device__ __align__(16) unsigned g_p4e[S4*S4*256];
__device__ __align__(16) float    g_p4v[S4*S4*256];
__device__ float    g_h[32];

// ---------------- helpers ----------------
__device__ __forceinline__ unsigned encf(float f) {
    unsigned u = __float_as_uint(f);
    return (u & 0x80000000u) ? ~u : (u | 0x80000000u);
}
__device__ __forceinline__ float decf(unsigned u) {
    return __uint_as_float((u & 0x80000000u) ? (u & 0x7fffffffu) : ~u);
}
__device__ __forceinline__ float eluf(float x) {
    return x > 0.f ? x : expm1f(x);
}
__device__ __forceinline__ void pool_scatter8(unsigned* d, const float* a) {
#pragma unroll
    for (int i = 0; i < 8; i++) atomicMax(d + i, encf(eluf(a[i])));
}

// ---------------- K0: zero pool accumulators (grid cleared incrementally) ----------------
__global__ void k_zero() {
    size_t i  = (size_t)blockIdx.x * blockDim.x + threadIdx.x;
    size_t st = (size_t)gridDim.x * blockDim.x;
    uint4 z = make_uint4(0u, 0u, 0u, 0u);
    for (size_t j = i; j < (size_t)(S1*S1*10/4);   j += st) ((uint4*)g_p1e)[j] = z;
    for (size_t j = i; j < (size_t)(S2*S2*64/4);   j += st) ((uint4*)g_p2e)[j] = z;
    for (size_t j = i; j < (size_t)(S3*S3*128/4);  j += st) ((uint4*)g_p3e)[j] = z;
    for (size_t j = i; j < (size_t)(S4*S4*256/4);  j += st) ((uint4*)g_p4e)[j] = z;
    if (i == 0) g_cnt = 0;
}

// ---------------- K1: scatter points onto grid ----------------
__global__ void k_scatter(const int* __restrict__ coords,
                          const float* __restrict__ feat, int P) {
    int p = blockIdx.x * blockDim.x + threadIdx.x;
    if (p >= P) return;
    int r = coords[2*p], c = coords[2*p+1];
    atomicAdd(&g_x[r*S0 + c], feat[p]);   // duplicates add (matches .at[].add)
}

// ---------------- K2: conv1 (1->10) at active sites, fused ELU + maxpool scatter ----------------
__global__ void k_conv1(const int* __restrict__ coords,
                        const float* __restrict__ w1, int P) {
    int p = blockIdx.x * blockDim.x + threadIdx.x;
    if (p >= P) return;
    int r = coords[2*p], c = coords[2*p+1];
    float acc[10];
#pragma unroll
    for (int co = 0; co < 10; co++) acc[co] = 0.f;
#pragma unroll
    for (int dr = -2; dr <= 2; dr++) {
        int rr = r + dr;
        if ((unsigned)rr >= (unsigned)S0) continue;
#pragma unroll
        for (int dc = -2; dc <= 2; dc++) {
            int cc = c + dc;
            if ((unsigned)cc >= (unsigned)S0) continue;
            float v = g_x[rr*S0 + cc];
            if (v != 0.f) {
                int tap = (dr+2)*5 + (dc+2);
#pragma unroll
                for (int co = 0; co < 10; co++) acc[co] += v * w1[tap*10 + co];
            }
        }
    }
    int pc = (r/5)*S1 + (c/5);
    unsigned* dst = &g_p1e[pc*10];
#pragma unroll
    for (int co = 0; co < 10; co++)
        atomicMax(&dst[co], encf(eluf(acc[co])));
}

// ---------------- K3: clear only the scattered cells (grid back to all-zero) ----------------
__global__ void k_clearpts(const int* __restrict__ coords, int P) {
    int p = blockIdx.x * blockDim.x + threadIdx.x;
    if (p >= P) return;
    g_x[coords[2*p]*S0 + coords[2*p+1]] = 0.f;
}

// ---------------- decode encoded pool -> dense values (0 at inactive) ----------------
__global__ void k_decode(int which, int n) {
    const unsigned* e; float* v;
    switch (which) {
        case 0:  e = g_p1e; v = g_p1v; break;
        case 1:  e = g_p2e; v = g_p2v; break;
        case 2:  e = g_p3e; v = g_p3v; break;
        default: e = g_p4e; v = g_p4v; break;
    }
    int i = blockIdx.x * blockDim.x + threadIdx.x;
    if (i >= n) return;
    unsigned u = e[i];
    v[i] = u ? decf(u) : 0.f;
}

// ---------------- build active-cell list (warp-aggregated atomics) ----------------
__global__ void k_list() {
    int i = blockIdx.x * blockDim.x + threadIdx.x;
    bool act = (i < S1*S1) && (g_p1e[i*10] != 0u);
    unsigned m = __ballot_sync(0xffffffffu, act);
    if (!m) return;
    int lane = threadIdx.x & 31;
    int ldr  = __ffs(m) - 1;
    int base = 0;
    if (lane == ldr) base = atomicAdd(&g_cnt, __popc(m));
    base = __shfl_sync(0xffffffffu, base, ldr);
    if (act) g_list[base + __popc(m & ((1u << lane) - 1u))] = i;
}

// ---------------- K4: conv2 (10->64) over active cells, scalar FFMA, fused ELU + pool ----------------
// 256 threads: 32 cells x 8 cog-groups (8 couts each)
__global__ __launch_bounds__(256) void k_conv2(const float* __restrict__ w2) {
    __shared__ float in_s[32*251];
    __shared__ int   cs[32];
    __shared__ int   cv[32];
    int cnt  = g_cnt;
    int base = blockIdx.x * 32;
    if (base >= cnt) return;
    if (threadIdx.x < 32) {
        int idx = base + threadIdx.x;
        int ok  = idx < cnt;
        cs[threadIdx.x] = g_list[ok ? idx : base];
        cv[threadIdx.x] = ok;
    }
    __syncthreads();
    for (int t = threadIdx.x; t < 32*250; t += 256) {
        int j = t / 250, k = t - j*250;
        int tap = k / 10, ci = k - tap*10;
        int id = cs[j];
        int rr = id / S1 + tap/5 - 2;
        int cc = id % S1 + tap%5 - 2;
        float v = 0.f;
        if ((unsigned)rr < (unsigned)S1 && (unsigned)cc < (unsigned)S1)
            v = g_p1v[(rr*S1 + cc)*10 + ci];
        in_s[j*251 + k] = v;
    }
    __syncthreads();
    int cog  = threadIdx.x & 7;            // 8 groups x 8 couts
    int cell = threadIdx.x >> 3;
    const float* ip = &in_s[cell*251];
    const float4* wq = (const float4*)w2 + cog*2;  // weight row = 16 float4
    float a[8];
#pragma unroll
    for (int i = 0; i < 8; i++) a[i] = 0.f;
#pragma unroll 10
    for (int k = 0; k < 250; k++) {
        float v = ip[k];
        float4 q0 = wq[k*16];
        float4 q1 = wq[k*16 + 1];
        a[0] += v*q0.x; a[1] += v*q0.y; a[2] += v*q0.z; a[3] += v*q0.w;
        a[4] += v*q1.x; a[5] += v*q1.y; a[6] += v*q1.z; a[7] += v*q1.w;
    }
    if (cv[cell]) {
        int id = cs[cell];
        int pc = ((id/S1)/5)*S2 + (id%S1)/5;
        pool_scatter8(&g_p2e[pc*64 + cog*8], a);
    }
}

// ---------------- K6: conv3 (64->128) dense over 144^2, scalar FFMA, 2 cells/thread ----------------
// 512 threads: 32 row-pairs (8x8 cell tile) x 16 cog-groups (8 couts each)
__global__ __launch_bounds__(512) void k_conv3(const float* __restrict__ w3) {
    __shared__ float in_s[144*65];         // 12x12 window x 64ch, stride 65 (37.4KB)
    int r0 = blockIdx.y * 8, c0 = blockIdx.x * 8;
    for (int t = threadIdx.x; t < 144*64; t += 512) {
        int pos = t >> 6, ci = t & 63;
        int wr = pos / 12, wc = pos - wr*12;
        int gr = r0 - 2 + wr, gc = c0 - 2 + wc;
        float v = 0.f;
        if ((unsigned)gr < (unsigned)S2 && (unsigned)gc < (unsigned)S2)
            v = g_p2v[(gr*S2 + gc)*64 + ci];
        in_s[pos*65 + ci] = v;
    }
    __syncthreads();
    int cog  = threadIdx.x & 15;           // 16 groups x 8 couts
    int pair = threadIdx.x >> 4;           // 0..31: rows (2pr, 2pr+1), col pc
    int pr = pair >> 3, pc = pair & 7;
    float a[8], b[8];
#pragma unroll
    for (int i = 0; i < 8; i++) { a[i] = 0.f; b[i] = 0.f; }
    const float4* wb = (const float4*)w3 + cog*2;  // weight row = 32 float4
#pragma unroll 1
    for (int tap = 0; tap < 25; tap++) {
        const float* ip0 = &in_s[((2*pr + tap/5)*12 + (pc + tap%5))*65];
        const float* ip1 = ip0 + 12*65;
        const float4* wt = wb + (size_t)tap*64*32;
#pragma unroll 8
        for (int ci = 0; ci < 64; ci++) {
            float v0 = ip0[ci];
            float v1 = ip1[ci];
            float4 q0 = wt[ci*32];
            float4 q1 = wt[ci*32 + 1];
            a[0] += v0*q0.x; a[1] += v0*q0.y; a[2] += v0*q0.z; a[3] += v0*q0.w;
            a[4] += v0*q1.x; a[5] += v0*q1.y; a[6] += v0*q1.z; a[7] += v0*q1.w;
            b[0] += v1*q0.x; b[1] += v1*q0.y; b[2] += v1*q0.z; b[3] += v1*q0.w;
            b[4] += v1*q1.x; b[5] += v1*q1.y; b[6] += v1*q1.z; b[7] += v1*q1.w;
        }
    }
    int gr = r0 + 2*pr, gc = c0 + pc;
    if (g_p2e[(gr*S2 + gc)*64]) {
        int pcell = (gr>>2)*S3 + (gc>>2);
        pool_scatter8(&g_p3e[pcell*128 + cog*8], a);
    }
    gr++;
    if (g_p2e[(gr*S2 + gc)*64]) {
        int pcell = (gr>>2)*S3 + (gc>>2);
        pool_scatter8(&g_p3e[pcell*128 + cog*8], b);
    }
}

// ---------------- K8: conv4 (128->256) dense over 36^2, scalar FFMA, fused ELU + pool ----------------
// 512 threads: 16 cells (4x4 tile) x 32 cog-groups (8 couts each)
__global__ __launch_bounds__(512) void k_conv4(const float* __restrict__ w4) {
    __shared__ float in_s[64*128];         // 8x8 window x 128ch (broadcast reads, no pad)
    int r0 = blockIdx.y * 4, c0 = blockIdx.x * 4;
    for (int t = threadIdx.x; t < 64*128; t += 512) {
        int pos = t >> 7, ci = t & 127;
        int wr = pos >> 3, wc = pos & 7;
        int gr = r0 - 2 + wr, gc = c0 - 2 + wc;
        float v = 0.f;
        if ((unsigned)gr < (unsigned)S3 && (unsigned)gc < (unsigned)S3)
            v = g_p3v[(gr*S3 + gc)*128 + ci];
        in_s[pos*128 + ci] = v;
    }
    __syncthreads();
    int cog = threadIdx.x & 31, cell = threadIdx.x >> 5;
    int cr = cell >> 2, cc = cell & 3;
    float a[8];
#pragma unroll
    for (int i = 0; i < 8; i++) a[i] = 0.f;
    const float4* wb = (const float4*)w4 + cog*2;  // weight row = 64 float4
#pragma unroll 1
    for (int tap = 0; tap < 25; tap++) {
        const float* ip = &in_s[((cr + tap/5)*8 + (cc + tap%5))*128];
        const float4* wt = wb + (size_t)tap*128*64;
#pragma unroll 8
        for (int ci = 0; ci < 128; ci++) {
            float v = ip[ci];
            float4 q0 = wt[ci*64];
            float4 q1 = wt[ci*64 + 1];
            a[0] += v*q0.x; a[1] += v*q0.y; a[2] += v*q0.z; a[3] += v*q0.w;
            a[4] += v*q1.x; a[5] += v*q1.y; a[6] += v*q1.z; a[7] += v*q1.w;
        }
    }
    int gr = r0 + cr, gc = c0 + cc;
    if (g_p3e[(gr*S3 + gc)*128]) {
        int pc = (gr>>2)*S4 + (gc>>2);
        pool_scatter8(&g_p4e[pc*256 + cog*8], a);
    }
}

// ---------------- K10a: fc1 (20736 -> 32) + ELU. block j computes h[j] ----------------
__global__ __launch_bounds__(256) void k_fc1(const float* __restrict__ w,
                                             const float* __restrict__ b) {
    int j = blockIdx.x;                    // 0..31
    float s0 = 0.f, s1 = 0.f, s2 = 0.f, s3 = 0.f;
    for (int i = threadIdx.x; i < 20736; i += 1024) {
        int i0 = i, i1 = i + 256, i2 = i + 512, i3 = i + 768;
        { int c = i0/81, rem = i0 - c*81; s0 += g_p4v[rem*256 + c] * w[i0*32 + j]; }
        if (i1 < 20736) { int c = i1/81, rem = i1 - c*81; s1 += g_p4v[rem*256 + c] * w[i1*32 + j]; }
        if (i2 < 20736) { int c = i2/81, rem = i2 - c*81; s2 += g_p4v[rem*256 + c] * w[i2*32 + j]; }
        if (i3 < 20736) { int c = i3/81, rem = i3 - c*81; s3 += g_p4v[rem*256 + c] * w[i3*32 + j]; }
    }
    float s = (s0 + s1) + (s2 + s3);
    __shared__ float red[256];
    red[threadIdx.x] = s;
    __syncthreads();
    for (int o = 128; o > 0; o >>= 1) {
        if (threadIdx.x < o) red[threadIdx.x] += red[threadIdx.x + o];
        __syncthreads();
    }
    if (threadIdx.x == 0) {
        float z = red[0] + b[j];
        g_h[j] = z > 0.f ? z : expm1f(z);
    }
}

// ---------------- K10b: fc2 (32 -> 5) + softmax ----------------
__global__ void k_fc2(const float* __restrict__ w, const float* __restrict__ b,
                      float* __restrict__ out) {
    if (threadIdx.x == 0) {
        float lg[5];
#pragma unroll
        for (int t = 0; t < 5; t++) lg[t] = b[t];
        for (int j = 0; j < 32; j++) {
            float h = g_h[j];
#pragma unroll
            for (int t = 0; t < 5; t++) lg[t] += h * w[j*5 + t];
        }
        float m = lg[0];
#pragma unroll
        for (int t = 1; t < 5; t++) m = fmaxf(m, lg[t]);
        float e[5], sum = 0.f;
#pragma unroll
        for (int t = 0; t < 5; t++) { e[t] = expf(lg[t] - m); sum += e[t]; }
        float inv = 1.f / sum;
#pragma unroll
        for (int t = 0; t < 5; t++) out[t] = e[t] * inv;
    }
}

// ---------------- launch ----------------
extern "C" void kernel_launch(void* const* d_in, const int* in_sizes, int n_in,
                              void* d_out, int out_size) {
    const int*   coords = (const int*)  d_in[0];
    const float* feats  = (const float*)d_in[1];
    const float* w1     = (const float*)d_in[2];
    const float* w2     = (const float*)d_in[3];
    const float* w3     = (const float*)d_in[4];
    const float* w4     = (const float*)d_in[5];
    const float* fc1w   = (const float*)d_in[6];
    const float* fc1b   = (const float*)d_in[7];
    const float* fc2w   = (const float*)d_in[8];
    const float* fc2b   = (const float*)d_in[9];
    float* out = (float*)d_out;
    int P = in_sizes[1];                  // number of points

    k_zero<<<2048, 256>>>();
    k_scatter<<<(P + 255)/256, 256>>>(coords, feats, P);
    k_conv1<<<(P + 127)/128, 128>>>(coords, w1, P);
    k_clearpts<<<(P + 255)/256, 256>>>(coords, P);
    k_decode<<<(S1*S1*10 + 255)/256, 256>>>(0, S1*S1*10);
    k_list<<<(S1*S1 + 255)/256, 256>>>();
    k_conv2<<<(S1*S1 + 31)/32, 256>>>(w2);
    k_decode<<<(S2*S2*64 + 255)/256, 256>>>(1, S2*S2*64);
    k_conv3<<<dim3(S2/8, S2/8), 512>>>(w3);
    k_decode<<<(S3*S3*128 + 255)/256, 256>>>(2, S3*S3*128);
    k_conv4<<<dim3(S3/4, S3/4), 512>>>(w4);
    k_decode<<<(S4*S4*256 + 255)/256, 256>>>(3, S4*S4*256);
    k_fc1<<<32, 256>>>(fc1w, fc1b);
    k_fc2<<<1, 32>>>(fc2w, fc2b, out);
}

// round 6
// speedup vs baseline: 1.0303x; 1.0303x over previous
#include <cuda_runtime.h>
#include <math.h>

#define S0 3600
#define S1 720
#define S2 144
#define S3 36
#define S4 9

// ---------------- static device scratch (no runtime allocation) ----------------
__device__ __align__(16) float    g_x   [S0*S0];        // 51.8MB dense scattered input grid
__device__ __align__(16) unsigned g_p1e [S1*S1*10];     // encoded pool accumulators (level1)
__device__ __align__(16) float    g_p1v [S1*S1*10];     // decoded values (0 at inactive)
__device__ __align__(16) int      g_list[S1*S1];        // active cell list at level1
__device__ __align__(16) int      g_inv [S1*S1];        // cell -> list index
__device__ __align__(16) int      g_act1[S1*S1];        // level1 activity
__device__ int      g_cnt;
__device__ __align__(16) float    g_c2out[S1*S1*64];    // conv2 raw outputs by list idx (132.7MB)
__device__ __align__(16) float    g_p2v [S2*S2*64];     // pooled level2 values
__device__ __align__(16) int      g_act2[S2*S2];
__device__ __align__(16) unsigned g_p3e [S3*S3*128];
__device__ __align__(16) float    g_p3v [S3*S3*128];
__device__ __align__(16) int      g_act3[S3*S3];
__device__ __align__(16) float    g_p4v [S4*S4*256];
__device__ float    g_h[32];

// ---------------- helpers ----------------
__device__ __forceinline__ unsigned encf(float f) {
    unsigned u = __float_as_uint(f);
    return (u & 0x80000000u) ? ~u : (u | 0x80000000u);
}
__device__ __forceinline__ float decf(unsigned u) {
    return __uint_as_float((u & 0x80000000u) ? (u & 0x7fffffffu) : ~u);
}
__device__ __forceinline__ float eluf(float x) {
    return x > 0.f ? x : expm1f(x);
}

// ---------------- K0: scatter points onto grid ----------------
__global__ void k_scatter(const int* __restrict__ coords,
                          const float* __restrict__ feat, int P) {
    int p = blockIdx.x * blockDim.x + threadIdx.x;
    if (p >= P) return;
    int r = coords[2*p], c = coords[2*p+1];
    atomicAdd(&g_x[r*S0 + c], feat[p]);   // duplicates add (matches .at[].add)
}

// ---------------- K1: conv1 (1->10) at active sites, fused ELU + maxpool scatter ----------------
__global__ void k_conv1(const int* __restrict__ coords,
                        const float* __restrict__ w1, int P) {
    int p = blockIdx.x * blockDim.x + threadIdx.x;
    if (p >= P) return;
    int r = coords[2*p], c = coords[2*p+1];
    float acc[10];
#pragma unroll
    for (int co = 0; co < 10; co++) acc[co] = 0.f;
#pragma unroll
    for (int dr = -2; dr <= 2; dr++) {
        int rr = r + dr;
        if ((unsigned)rr >= (unsigned)S0) continue;
#pragma unroll
        for (int dc = -2; dc <= 2; dc++) {
            int cc = c + dc;
            if ((unsigned)cc >= (unsigned)S0) continue;
            float v = g_x[rr*S0 + cc];
            if (v != 0.f) {
                int tap = (dr+2)*5 + (dc+2);
#pragma unroll
                for (int co = 0; co < 10; co++) acc[co] += v * w1[tap*10 + co];
            }
        }
    }
    int pc = (r/5)*S1 + (c/5);
    unsigned* dst = &g_p1e[pc*10];
#pragma unroll
    for (int co = 0; co < 10; co++)
        atomicMax(&dst[co], encf(eluf(acc[co])));
}

// ---------------- K2: decode level1 + build list/inv/act + clear p1e ----------------
// one thread per S1 cell; 518400 = 2025 * 256 exactly
__global__ __launch_bounds__(256) void k_decode0() {
    int cell = blockIdx.x * blockDim.x + threadIdx.x;
    unsigned u0 = g_p1e[cell*10];
    bool act = (u0 != 0u);
    unsigned m = __ballot_sync(0xffffffffu, act);
    int idx = 0;
    if (m) {
        int lane = threadIdx.x & 31;
        int ldr  = __ffs(m) - 1;
        int base = 0;
        if (lane == ldr) base = atomicAdd(&g_cnt, __popc(m));
        base = __shfl_sync(0xffffffffu, base, ldr);
        idx = base + __popc(m & ((1u << lane) - 1u));
    }
    g_act1[cell] = act ? 1 : 0;
    if (act) { g_inv[cell] = idx; g_list[idx] = cell; }
#pragma unroll
    for (int j = 0; j < 10; j++) {
        unsigned u = g_p1e[cell*10 + j];
        g_p1v[cell*10 + j] = u ? decf(u) : 0.f;
        g_p1e[cell*10 + j] = 0u;
    }
}

// ---------------- K3: conv2 (10->64) over active cells -> dense raw store (NO atomics) ----------------
// 256 threads: 32 cells x 8 cog-groups (8 couts each)
__global__ __launch_bounds__(256) void k_conv2(const float* __restrict__ w2) {
    __shared__ float in_s[32*251];
    __shared__ int   cs[32];
    __shared__ int   cv[32];
    int cnt  = g_cnt;
    int base = blockIdx.x * 32;
    if (base >= cnt) return;
    if (threadIdx.x < 32) {
        int idx = base + threadIdx.x;
        int ok  = idx < cnt;
        cs[threadIdx.x] = g_list[ok ? idx : base];
        cv[threadIdx.x] = ok;
    }
    __syncthreads();
    for (int t = threadIdx.x; t < 32*250; t += 256) {
        int j = t / 250, k = t - j*250;
        int tap = k / 10, ci = k - tap*10;
        int id = cs[j];
        int rr = id / S1 + tap/5 - 2;
        int cc = id % S1 + tap%5 - 2;
        float v = 0.f;
        if ((unsigned)rr < (unsigned)S1 && (unsigned)cc < (unsigned)S1)
            v = g_p1v[(rr*S1 + cc)*10 + ci];
        in_s[j*251 + k] = v;
    }
    __syncthreads();
    int cog  = threadIdx.x & 7;            // 8 groups x 8 couts
    int cell = threadIdx.x >> 3;
    const float* ip = &in_s[cell*251];
    const float4* wq = (const float4*)w2 + cog*2;  // weight row = 16 float4
    float a[8];
#pragma unroll
    for (int i = 0; i < 8; i++) a[i] = 0.f;
#pragma unroll 10
    for (int k = 0; k < 250; k++) {
        float v = ip[k];
        float4 q0 = wq[k*16];
        float4 q1 = wq[k*16 + 1];
        a[0] += v*q0.x; a[1] += v*q0.y; a[2] += v*q0.z; a[3] += v*q0.w;
        a[4] += v*q1.x; a[5] += v*q1.y; a[6] += v*q1.z; a[7] += v*q1.w;
    }
    if (cv[cell]) {
        // store RAW accumulators at list index (elu applied after pooling: elu monotone)
        float* o = &g_c2out[(base + cell)*64 + cog*8];
        *(float4*)(o)     = make_float4(a[0], a[1], a[2], a[3]);
        *(float4*)(o + 4) = make_float4(a[4], a[5], a[6], a[7]);
    }
}

// ---------------- K4: gather-pool 5x5 level1->level2 + ELU + act2 (+ reset cnt) ----------------
// one thread per (S2 cell, 4-cout group): 20736*16 = 331776 = 1296 * 256
__global__ __launch_bounds__(256) void k_decode1() {
    int t = blockIdx.x * blockDim.x + threadIdx.x;
    int cell = t >> 4, cg = t & 15;
    int r2 = cell / S2, c2 = cell - r2*S2;
    float m0 = -1e30f, m1 = -1e30f, m2 = -1e30f, m3 = -1e30f;
    bool any = false;
#pragma unroll
    for (int dr = 0; dr < 5; dr++) {
#pragma unroll
        for (int dc = 0; dc < 5; dc++) {
            int cid = (r2*5 + dr)*S1 + (c2*5 + dc);
            if (g_act1[cid]) {
                any = true;
                const float4 v = *(const float4*)&g_c2out[g_inv[cid]*64 + cg*4];
                m0 = fmaxf(m0, v.x); m1 = fmaxf(m1, v.y);
                m2 = fmaxf(m2, v.z); m3 = fmaxf(m3, v.w);
            }
        }
    }
    float4 o;
    if (any) o = make_float4(eluf(m0), eluf(m1), eluf(m2), eluf(m3));
    else     o = make_float4(0.f, 0.f, 0.f, 0.f);
    *(float4*)&g_p2v[cell*64 + cg*4] = o;
    if (cg == 0) g_act2[cell] = any ? 1 : 0;
    if (t == 0) g_cnt = 0;                 // ready for next replay's decode0
}

// ---------------- K5: conv3 (64->128) dense over 144^2, 4 cells/thread, local-max pool ----------------
// 256 threads: 16 cogs (8 couts) x 16 thread-cells; each thread owns 4 rows x 1 col = 1 pool cell
__global__ __launch_bounds__(256) void k_conv3(const float* __restrict__ w3) {
    __shared__ float in_s[144*65];         // 12x12 window x 64ch, stride 65 (37.4KB)
    int r0 = blockIdx.y * 8, c0 = blockIdx.x * 8;
    for (int t = threadIdx.x; t < 144*64; t += 256) {
        int pos = t >> 6, ci = t & 63;
        int wr = pos / 12, wc = pos - wr*12;
        int gr = r0 - 2 + wr, gc = c0 - 2 + wc;
        float v = 0.f;
        if ((unsigned)gr < (unsigned)S2 && (unsigned)gc < (unsigned)S2)
            v = g_p2v[(gr*S2 + gc)*64 + ci];
        in_s[pos*65 + ci] = v;
    }
    __syncthreads();
    int cog   = threadIdx.x & 15;          // 16 groups x 8 couts
    int tcell = threadIdx.x >> 4;          // 0..15
    int pr = tcell >> 3, pc = tcell & 7;   // rows 4pr..4pr+3, col pc
    float acc[4][8];
#pragma unroll
    for (int k = 0; k < 4; k++)
#pragma unroll
        for (int j = 0; j < 8; j++) acc[k][j] = 0.f;
    const float4* wb = (const float4*)w3 + cog*2;  // weight row = 32 float4
#pragma unroll 1
    for (int tap = 0; tap < 25; tap++) {
        const float* ip = &in_s[((4*pr + tap/5)*12 + (pc + tap%5))*65];
        const float4* wt = wb + (size_t)tap*64*32;
#pragma unroll 4
        for (int ci = 0; ci < 64; ci++) {
            float4 q0 = wt[ci*32];
            float4 q1 = wt[ci*32 + 1];
            float v0 = ip[ci];
            float v1 = ip[ci + 12*65];
            float v2 = ip[ci + 2*12*65];
            float v3 = ip[ci + 3*12*65];
            acc[0][0] += v0*q0.x; acc[0][1] += v0*q0.y; acc[0][2] += v0*q0.z; acc[0][3] += v0*q0.w;
            acc[0][4] += v0*q1.x; acc[0][5] += v0*q1.y; acc[0][6] += v0*q1.z; acc[0][7] += v0*q1.w;
            acc[1][0] += v1*q0.x; acc[1][1] += v1*q0.y; acc[1][2] += v1*q0.z; acc[1][3] += v1*q0.w;
            acc[1][4] += v1*q1.x; acc[1][5] += v1*q1.y; acc[1][6] += v1*q1.z; acc[1][7] += v1*q1.w;
            acc[2][0] += v2*q0.x; acc[2][1] += v2*q0.y; acc[2][2] += v2*q0.z; acc[2][3] += v2*q0.w;
            acc[2][4] += v2*q1.x; acc[2][5] += v2*q1.y; acc[2][6] += v2*q1.z; acc[2][7] += v2*q1.w;
            acc[3][0] += v3*q0.x; acc[3][1] += v3*q0.y; acc[3][2] += v3*q0.z; acc[3][3] += v3*q0.w;
            acc[3][4] += v3*q1.x; acc[3][5] += v3*q1.y; acc[3][6] += v3*q1.z; acc[3][7] += v3*q1.w;
        }
    }
    // the 4 cells (rows r0+4pr..+3, col c0+pc) all pool into ONE level-3 cell
    float m[8];
#pragma unroll
    for (int j = 0; j < 8; j++) m[j] = -1e30f;
    bool any = false;
#pragma unroll
    for (int k = 0; k < 4; k++) {
        int gr = r0 + 4*pr + k, gc = c0 + pc;
        if (g_act2[gr*S2 + gc]) {
            any = true;
#pragma unroll
            for (int j = 0; j < 8; j++) m[j] = fmaxf(m[j], acc[k][j]);
        }
    }
    if (any) {
        int p3 = ((r0 + 4*pr) >> 2)*S3 + ((c0 + pc) >> 2);
        unsigned* d = &g_p3e[p3*128 + cog*8];
#pragma unroll
        for (int j = 0; j < 8; j++) atomicMax(d + j, encf(eluf(m[j])));
    }
}

// ---------------- K6: decode level3 + act3 + clear p3e ----------------
__global__ __launch_bounds__(256) void k_decode2() {
    int i = blockIdx.x * blockDim.x + threadIdx.x;
    if (i >= S3*S3*128) return;
    unsigned u = g_p3e[i];
    g_p3v[i] = u ? decf(u) : 0.f;
    g_p3e[i] = 0u;
    if ((i & 127) == 0) g_act3[i >> 7] = (u != 0u) ? 1 : 0;
}

// ---------------- K7: conv4 (128->256) dense over 36^2; block = one pool cell; smem max; direct write ----------------
// 512 threads: 16 cells (4x4 tile) x 32 cog-groups (8 couts each)
__global__ __launch_bounds__(512) void k_conv4(const float* __restrict__ w4) {
    __shared__ float    in_s[64*128];      // 8x8 window x 128ch (32KB)
    __shared__ unsigned se[256];           // encoded per-cout max over the 16 cells
    if (threadIdx.x < 256) se[threadIdx.x] = 0u;
    int r0 = blockIdx.y * 4, c0 = blockIdx.x * 4;
    for (int t = threadIdx.x; t < 64*128; t += 512) {
        int pos = t >> 7, ci = t & 127;
        int wr = pos >> 3, wc = pos & 7;
        int gr = r0 - 2 + wr, gc = c0 - 2 + wc;
        float v = 0.f;
        if ((unsigned)gr < (unsigned)S3 && (unsigned)gc < (unsigned)S3)
            v = g_p3v[(gr*S3 + gc)*128 + ci];
        in_s[pos*128 + ci] = v;
    }
    __syncthreads();
    int cog = threadIdx.x & 31, cell = threadIdx.x >> 5;
    int cr = cell >> 2, cc = cell & 3;
    float a[8];
#pragma unroll
    for (int i = 0; i < 8; i++) a[i] = 0.f;
    const float4* wb = (const float4*)w4 + cog*2;  // weight row = 64 float4
#pragma unroll 1
    for (int tap = 0; tap < 25; tap++) {
        const float* ip = &in_s[((cr + tap/5)*8 + (cc + tap%5))*128];
        const float4* wt = wb + (size_t)tap*128*64;
#pragma unroll 4
        for (int ci = 0; ci < 128; ci++) {
            float v = ip[ci];
            float4 q0 = wt[ci*64];
            float4 q1 = wt[ci*64 + 1];
            a[0] += v*q0.x; a[1] += v*q0.y; a[2] += v*q0.z; a[3] += v*q0.w;
            a[4] += v*q1.x; a[5] += v*q1.y; a[6] += v*q1.z; a[7] += v*q1.w;
        }
    }
    if (g_act3[(r0 + cr)*S3 + (c0 + cc)]) {
        unsigned* d = &se[cog*8];
#pragma unroll
        for (int j = 0; j < 8; j++) atomicMax(d + j, encf(a[j]));  // raw; elu after max
    }
    __syncthreads();
    if (threadIdx.x < 256) {
        unsigned u = se[threadIdx.x];
        g_p4v[(blockIdx.y*S4 + blockIdx.x)*256 + threadIdx.x] = u ? eluf(decf(u)) : 0.f;
    }
}

// ---------------- K8: fc1 (20736 -> 32) + ELU. block j computes h[j] ----------------
__global__ __launch_bounds__(256) void k_fc1(const float* __restrict__ w,
                                             const float* __restrict__ b) {
    int j = blockIdx.x;                    // 0..31
    float s0 = 0.f, s1 = 0.f, s2 = 0.f, s3 = 0.f;
    for (int i = threadIdx.x; i < 20736; i += 1024) {
        int i0 = i, i1 = i + 256, i2 = i + 512, i3 = i + 768;
        { int c = i0/81, rem = i0 - c*81; s0 += g_p4v[rem*256 + c] * w[i0*32 + j]; }
        if (i1 < 20736) { int c = i1/81, rem = i1 - c*81; s1 += g_p4v[rem*256 + c] * w[i1*32 + j]; }
        if (i2 < 20736) { int c = i2/81, rem = i2 - c*81; s2 += g_p4v[rem*256 + c] * w[i2*32 + j]; }
        if (i3 < 20736) { int c = i3/81, rem = i3 - c*81; s3 += g_p4v[rem*256 + c] * w[i3*32 + j]; }
    }
    float s = (s0 + s1) + (s2 + s3);
    __shared__ float red[256];
    red[threadIdx.x] = s;
    __syncthreads();
    for (int o = 128; o > 0; o >>= 1) {
        if (threadIdx.x < o) red[threadIdx.x] += red[threadIdx.x + o];
        __syncthreads();
    }
    if (threadIdx.x == 0) {
        float z = red[0] + b[j];
        g_h[j] = z > 0.f ? z : expm1f(z);
    }
}

// ---------------- K9: fc2 (32 -> 5) + softmax ----------------
__global__ void k_fc2(const float* __restrict__ w, const float* __restrict__ b,
                      float* __restrict__ out) {
    if (threadIdx.x == 0) {
        float lg[5];
#pragma unroll
        for (int t = 0; t < 5; t++) lg[t] = b[t];
        for (int j = 0; j < 32; j++) {
            float h = g_h[j];
#pragma unroll
            for (int t = 0; t < 5; t++) lg[t] += h * w[j*5 + t];
        }
        float m = lg[0];
#pragma unroll
        for (int t = 1; t < 5; t++) m = fmaxf(m, lg[t]);
        float e[5], sum = 0.f;
#pragma unroll
        for (int t = 0; t < 5; t++) { e[t] = expf(lg[t] - m); sum += e[t]; }
        float inv = 1.f / sum;
#pragma unroll
        for (int t = 0; t < 5; t++) out[t] = e[t] * inv;
    }
}

// ---------------- K10: clear only the scattered cells (grid back to all-zero) ----------------
__global__ void k_clearpts(const int* __restrict__ coords, int P) {
    int p = blockIdx.x * blockDim.x + threadIdx.x;
    if (p >= P) return;
    g_x[coords[2*p]*S0 + coords[2*p+1]] = 0.f;
}

// ---------------- launch ----------------
extern "C" void kernel_launch(void* const* d_in, const int* in_sizes, int n_in,
                              void* d_out, int out_size) {
    const int*   coords = (const int*)  d_in[0];
    const float* feats  = (const float*)d_in[1];
    const float* w1     = (const float*)d_in[2];
    const float* w2     = (const float*)d_in[3];
    const float* w3     = (const float*)d_in[4];
    const float* w4     = (const float*)d_in[5];
    const float* fc1w   = (const float*)d_in[6];
    const float* fc1b   = (const float*)d_in[7];
    const float* fc2w   = (const float*)d_in[8];
    const float* fc2b   = (const float*)d_in[9];
    float* out = (float*)d_out;
    int P = in_sizes[1];                  // number of points

    k_scatter<<<(P + 255)/256, 256>>>(coords, feats, P);        // 0
    k_conv1<<<(P + 127)/128, 128>>>(coords, w1, P);             // 1
    k_decode0<<<S1*S1/256, 256>>>();                            // 2
    k_conv2<<<(S1*S1 + 31)/32, 256>>>(w2);                      // 3  <- profiled slot
    k_decode1<<<S2*S2*16/256, 256>>>();                         // 4
    k_conv3<<<dim3(S2/8, S2/8), 256>>>(w3);                     // 5
    k_decode2<<<(S3*S3*128 + 255)/256, 256>>>();                // 6
    k_conv4<<<dim3(S3/4, S3/4), 512>>>(w4);                     // 7
    k_fc1<<<32, 256>>>(fc1w, fc1b);                             // 8
    k_fc2<<<1, 32>>>(fc2w, fc2b, out);                          // 9
    k_clearpts<<<(P + 255)/256, 256>>>(coords, P);              // 10
}

// round 11
// speedup vs baseline: 2.1581x; 2.0947x over previous
#include <cuda_runtime.h>
#include <math.h>

#define S0 3600
#define S1 720
#define S2 144
#define S3 36
#define S4 9

// ---------------- static device scratch ----------------
__device__ __align__(16) float    g_x   [S0*S0];        // 51.8MB dense scattered input grid
__device__ __align__(16) unsigned g_p1e [S1*S1*10];     // encoded pool accumulators (level1)
__device__ __align__(16) float    g_p1v [S1*S1*10];     // decoded values (0 at inactive)
__device__ __align__(16) int      g_list[S1*S1];        // active cell list at level1
__device__ __align__(16) int      g_inv [S1*S1];        // cell -> list index
__device__ __align__(16) int      g_act1[S1*S1];        // level1 activity
__device__ int      g_cnt;
__device__ __align__(16) float    g_c2out[S1*S1*64];    // conv2 raw outputs by list idx
__device__ __align__(16) float    g_p2v [S2*S2*64];     // pooled level2 values
__device__ __align__(16) int      g_act2[S2*S2];
__device__ __align__(16) float    g_p3v [S3*S3*128];    // pooled level3 values
__device__ __align__(16) int      g_act3[S3*S3];
__device__ __align__(16) float    g_p4v [S4*S4*256];
__device__ float    g_h[32];

// ---------------- helpers ----------------
__device__ __forceinline__ unsigned encf(float f) {
    unsigned u = __float_as_uint(f);
    return (u & 0x80000000u) ? ~u : (u | 0x80000000u);
}
__device__ __forceinline__ float decf(unsigned u) {
    return __uint_as_float((u & 0x80000000u) ? (u & 0x7fffffffu) : ~u);
}
__device__ __forceinline__ float eluf(float x) {
    return x > 0.f ? x : expm1f(x);
}

// ---------------- K0: scatter points onto grid ----------------
__global__ void k_scatter(const int* __restrict__ coords,
                          const float* __restrict__ feat, int P) {
    int p = blockIdx.x * blockDim.x + threadIdx.x;
    if (p >= P) return;
    int r = coords[2*p], c = coords[2*p+1];
    atomicAdd(&g_x[r*S0 + c], feat[p]);
}

// ---------------- K1: conv1 (1->10) at active sites, fused ELU + maxpool scatter ----------------
__global__ void k_conv1(const int* __restrict__ coords,
                        const float* __restrict__ w1, int P) {
    int p = blockIdx.x * blockDim.x + threadIdx.x;
    if (p >= P) return;
    int r = coords[2*p], c = coords[2*p+1];
    float acc[10];
#pragma unroll
    for (int co = 0; co < 10; co++) acc[co] = 0.f;
#pragma unroll
    for (int dr = -2; dr <= 2; dr++) {
        int rr = r + dr;
        if ((unsigned)rr >= (unsigned)S0) continue;
#pragma unroll
        for (int dc = -2; dc <= 2; dc++) {
            int cc = c + dc;
            if ((unsigned)cc >= (unsigned)S0) continue;
            float v = g_x[rr*S0 + cc];
            if (v != 0.f) {
                int tap = (dr+2)*5 + (dc+2);
#pragma unroll
                for (int co = 0; co < 10; co++) acc[co] += v * w1[tap*10 + co];
            }
        }
    }
    int pc = (r/5)*S1 + (c/5);
    unsigned* dst = &g_p1e[pc*10];
#pragma unroll
    for (int co = 0; co < 10; co++)
        atomicMax(&dst[co], encf(eluf(acc[co])));
}

// ---------------- K2: decode level1 + build list/inv/act + clear p1e ----------------
__global__ __launch_bounds__(256) void k_decode0() {
    int cell = blockIdx.x * blockDim.x + threadIdx.x;
    unsigned u0 = g_p1e[cell*10];
    bool act = (u0 != 0u);
    unsigned m = __ballot_sync(0xffffffffu, act);
    int idx = 0;
    if (m) {
        int lane = threadIdx.x & 31;
        int ldr  = __ffs(m) - 1;
        int base = 0;
        if (lane == ldr) base = atomicAdd(&g_cnt, __popc(m));
        base = __shfl_sync(0xffffffffu, base, ldr);
        idx = base + __popc(m & ((1u << lane) - 1u));
    }
    g_act1[cell] = act ? 1 : 0;
    if (act) { g_inv[cell] = idx; g_list[idx] = cell; }
#pragma unroll
    for (int j = 0; j < 10; j++) {
        unsigned u = g_p1e[cell*10 + j];
        g_p1v[cell*10 + j] = u ? decf(u) : 0.f;
        g_p1e[cell*10 + j] = 0u;
    }
}

// ---------------- K3: conv2 (10->64) GEMM-tiled: 64 cells x 64 couts, thread 4x4 ----------------
__global__ __launch_bounds__(256) void k_conv2(const float* __restrict__ w2) {
    __shared__ float A_t[50*64];           // [kk][cell] 12.8KB
    __shared__ float w_s[50*64];           // [kk][co]   12.8KB
    __shared__ int   cs[64];
    __shared__ int   cv[64];
    int cnt  = g_cnt;
    int base = blockIdx.x * 64;
    if (base >= cnt) return;
    if (threadIdx.x < 64) {
        int idx = base + threadIdx.x;
        int ok  = idx < cnt;
        cs[threadIdx.x] = g_list[ok ? idx : base];
        cv[threadIdx.x] = ok;
    }
    int tx = threadIdx.x & 15;             // co group: co = tx*4
    int ty = threadIdx.x >> 4;             // cell group: cells ty*4..+3
    float acc[4][4];
#pragma unroll
    for (int q = 0; q < 4; q++)
#pragma unroll
        for (int j = 0; j < 4; j++) acc[q][j] = 0.f;

    for (int tr = 0; tr < 5; tr++) {       // K chunks of 50 (one tap-row)
        __syncthreads();
        // stage weights: rows kk = tc*10+ci -> w2[(tr*50+kk)*64+co]
        {
            const float4* wp = (const float4*)(w2 + tr*50*64);
            for (int t = threadIdx.x; t < 50*64/4; t += 256)
                ((float4*)w_s)[t] = wp[t];
        }
        // gather A: [kk][cell], cell fast (contiguous STS)
        for (int t = threadIdx.x; t < 50*64; t += 256) {
            int cell = t & 63, kk = t >> 6;
            int tc = kk / 10, ci = kk - tc*10;
            int id = cs[cell];
            int rr = id / S1 + tr - 2;
            int cc = id % S1 + tc - 2;
            float v = 0.f;
            if ((unsigned)rr < (unsigned)S1 && (unsigned)cc < (unsigned)S1)
                v = g_p1v[(rr*S1 + cc)*10 + ci];
            A_t[kk*64 + cell] = v;
        }
        __syncthreads();
#pragma unroll 5
        for (int kk = 0; kk < 50; kk++) {
            float4 av = *(const float4*)&A_t[kk*64 + ty*4];
            float4 bv = *(const float4*)&w_s[kk*64 + tx*4];
            acc[0][0] += av.x*bv.x; acc[0][1] += av.x*bv.y; acc[0][2] += av.x*bv.z; acc[0][3] += av.x*bv.w;
            acc[1][0] += av.y*bv.x; acc[1][1] += av.y*bv.y; acc[1][2] += av.y*bv.z; acc[1][3] += av.y*bv.w;
            acc[2][0] += av.z*bv.x; acc[2][1] += av.z*bv.y; acc[2][2] += av.z*bv.z; acc[2][3] += av.z*bv.w;
            acc[3][0] += av.w*bv.x; acc[3][1] += av.w*bv.y; acc[3][2] += av.w*bv.z; acc[3][3] += av.w*bv.w;
        }
    }
#pragma unroll
    for (int q = 0; q < 4; q++) {
        int cell = ty*4 + q;
        if (cv[cell]) {
            *(float4*)&g_c2out[(base + cell)*64 + tx*4] =
                make_float4(acc[q][0], acc[q][1], acc[q][2], acc[q][3]);
        }
    }
}

// ---------------- K4: gather-pool 5x5 level1->level2 + ELU + act2 (+ reset cnt) ----------------
__global__ __launch_bounds__(256) void k_decode1() {
    int t = blockIdx.x * blockDim.x + threadIdx.x;
    int cell = t >> 4, cg = t & 15;
    int r2 = cell / S2, c2 = cell - r2*S2;
    float m0 = -1e30f, m1 = -1e30f, m2 = -1e30f, m3 = -1e30f;
    bool any = false;
#pragma unroll
    for (int dr = 0; dr < 5; dr++) {
#pragma unroll
        for (int dc = 0; dc < 5; dc++) {
            int cid = (r2*5 + dr)*S1 + (c2*5 + dc);
            if (g_act1[cid]) {
                any = true;
                const float4 v = *(const float4*)&g_c2out[g_inv[cid]*64 + cg*4];
                m0 = fmaxf(m0, v.x); m1 = fmaxf(m1, v.y);
                m2 = fmaxf(m2, v.z); m3 = fmaxf(m3, v.w);
            }
        }
    }
    float4 o;
    if (any) o = make_float4(eluf(m0), eluf(m1), eluf(m2), eluf(m3));
    else     o = make_float4(0.f, 0.f, 0.f, 0.f);
    *(float4*)&g_p2v[cell*64 + cg*4] = o;
    if (cg == 0) g_act2[cell] = any ? 1 : 0;
    if (t == 0) g_cnt = 0;
}

// ---------------- K5: conv3 (64->128) GEMM-tiled over 8x8 cells, smem weights, in-block pool ----------------
// 256 threads: tx=co group (8 couts), ty: col (0..7) + row-half; thread = 4 rows x 1 col = 1 pool cell
#define SMEM3_BYTES ((64*145 + 64*128)*4 + 512*4)
__global__ __launch_bounds__(256) void k_conv3(const float* __restrict__ w3) {
    extern __shared__ float smem3[];
    float*    in_t = smem3;                        // [64 ci][145 pos(144+1)]
    float*    w_s  = smem3 + 64*145;               // [64 ci][128 co]
    unsigned* se   = (unsigned*)(w_s + 64*128);    // [4 pool][128 co]
    int r0 = blockIdx.y * 8, c0 = blockIdx.x * 8;
    // gather input window 12x12 x 64ch (transposed), zero-padded
    for (int t = threadIdx.x; t < 144*64; t += 256) {
        int ci = t & 63, pos = t >> 6;
        int wr = pos / 12, wc = pos - wr*12;
        int gr = r0 - 2 + wr, gc = c0 - 2 + wc;
        float v = 0.f;
        if ((unsigned)gr < (unsigned)S2 && (unsigned)gc < (unsigned)S2)
            v = g_p2v[(gr*S2 + gc)*64 + ci];
        in_t[ci*145 + pos] = v;
    }
    se[threadIdx.x] = 0u; se[threadIdx.x + 256] = 0u;
    int tx = threadIdx.x & 15;             // co = tx*8
    int ty = threadIdx.x >> 4;
    int rh = ty >> 3, cf = ty & 7;         // rows rh*4..+3, col cf
    int co = tx*8;
    float acc[4][8];
#pragma unroll
    for (int q = 0; q < 4; q++)
#pragma unroll
        for (int j = 0; j < 8; j++) acc[q][j] = 0.f;

    for (int tap = 0; tap < 25; tap++) {
        __syncthreads();
        // stage weights for this tap: [64 ci][128 co]
        {
            const float4* wp = (const float4*)(w3 + (size_t)tap*64*128);
            for (int t = threadIdx.x; t < 64*128/4; t += 256)
                ((float4*)w_s)[t] = wp[t];
        }
        __syncthreads();
        int tr = tap / 5, tc = tap - tr*5;
        int bp = (rh*4 + tr)*12 + cf + tc;
#pragma unroll 4
        for (int ci = 0; ci < 64; ci++) {
            float4 b0 = *(const float4*)&w_s[ci*128 + co];
            float4 b1 = *(const float4*)&w_s[ci*128 + co + 4];
            const float* ap = &in_t[ci*145 + bp];
            float a0 = ap[0], a1 = ap[12], a2 = ap[24], a3 = ap[36];
            acc[0][0] += a0*b0.x; acc[0][1] += a0*b0.y; acc[0][2] += a0*b0.z; acc[0][3] += a0*b0.w;
            acc[0][4] += a0*b1.x; acc[0][5] += a0*b1.y; acc[0][6] += a0*b1.z; acc[0][7] += a0*b1.w;
            acc[1][0] += a1*b0.x; acc[1][1] += a1*b0.y; acc[1][2] += a1*b0.z; acc[1][3] += a1*b0.w;
            acc[1][4] += a1*b1.x; acc[1][5] += a1*b1.y; acc[1][6] += a1*b1.z; acc[1][7] += a1*b1.w;
            acc[2][0] += a2*b0.x; acc[2][1] += a2*b0.y; acc[2][2] += a2*b0.z; acc[2][3] += a2*b0.w;
            acc[2][4] += a2*b1.x; acc[2][5] += a2*b1.y; acc[2][6] += a2*b1.z; acc[2][7] += a2*b1.w;
            acc[3][0] += a3*b0.x; acc[3][1] += a3*b0.y; acc[3][2] += a3*b0.z; acc[3][3] += a3*b0.w;
            acc[3][4] += a3*b1.x; acc[3][5] += a3*b1.y; acc[3][6] += a3*b1.z; acc[3][7] += a3*b1.w;
        }
    }
    // thread's 4 cells pool into one level-3 cell: local max gated by act2, smem-encoded
    {
        float mx[8];
#pragma unroll
        for (int j = 0; j < 8; j++) mx[j] = -1e30f;
        bool any = false;
#pragma unroll
        for (int q = 0; q < 4; q++) {
            int gr = r0 + rh*4 + q, gc = c0 + cf;
            if (g_act2[gr*S2 + gc]) {
                any = true;
#pragma unroll
                for (int j = 0; j < 8; j++) mx[j] = fmaxf(mx[j], acc[q][j]);
            }
        }
        if (any) {
            int pp = rh*2 + (cf >> 2);
            unsigned* d = &se[pp*128 + co];
#pragma unroll
            for (int j = 0; j < 8; j++) atomicMax(d + j, encf(mx[j]));
        }
    }
    __syncthreads();
    for (int e = threadIdx.x; e < 512; e += 256) {
        unsigned u = se[e];
        int pp = e >> 7, ch = e & 127;
        int pr = (r0 >> 2) + (pp >> 1), pc = (c0 >> 2) + (pp & 1);
        g_p3v[(pr*S3 + pc)*128 + ch] = u ? eluf(decf(u)) : 0.f;
        if (ch == 0) g_act3[pr*S3 + pc] = (u != 0u) ? 1 : 0;
    }
}

// ---------------- K6: conv4 (128->256) GEMM-tiled; block = one pool cell (4x4 cells) ----------------
// 256 threads: tx (0..63) co=tx*4; ty (0..3) = cell column; thread = 4 rows x 1 col x 4 couts
#define SMEM4_BYTES ((128*65 + 64*256)*4 + 256*4)
__global__ __launch_bounds__(256) void k_conv4(const float* __restrict__ w4) {
    extern __shared__ float smem4[];
    float*    in_t = smem4;                        // [128 ci][65 pos(64+1)]
    float*    w_s  = smem4 + 128*65;               // [64 ci][256 co] (chunk)
    unsigned* se   = (unsigned*)(w_s + 64*256);    // [256 co]
    int r0 = blockIdx.y * 4, c0 = blockIdx.x * 4;
    // gather input window 8x8 x 128ch (transposed), zero-padded
    for (int t = threadIdx.x; t < 64*128; t += 256) {
        int ci = t & 127, pos = t >> 7;
        int wr = pos >> 3, wc = pos & 7;
        int gr = r0 - 2 + wr, gc = c0 - 2 + wc;
        float v = 0.f;
        if ((unsigned)gr < (unsigned)S3 && (unsigned)gc < (unsigned)S3)
            v = g_p3v[(gr*S3 + gc)*128 + ci];
        in_t[ci*65 + pos] = v;
    }
    se[threadIdx.x] = 0u;
    int tx = threadIdx.x & 63;             // co = tx*4
    int ty = threadIdx.x >> 6;             // cell column 0..3
    int co = tx*4;
    float acc[4][4];
#pragma unroll
    for (int q = 0; q < 4; q++)
#pragma unroll
        for (int j = 0; j < 4; j++) acc[q][j] = 0.f;

    for (int tap = 0; tap < 25; tap++) {
        int tr = tap / 5, tc = tap - tr*5;
        for (int cic = 0; cic < 2; cic++) {
            __syncthreads();
            // stage weight chunk [64 ci][256 co]
            {
                const float4* wp = (const float4*)(w4 + ((size_t)tap*128 + cic*64)*256);
                for (int t = threadIdx.x; t < 64*256/4; t += 256)
                    ((float4*)w_s)[t] = wp[t];
            }
            __syncthreads();
            int bp = tr*8 + ty + tc;
#pragma unroll 4
            for (int ci = 0; ci < 64; ci++) {
                float4 bv = *(const float4*)&w_s[ci*256 + co];
                const float* ap = &in_t[(cic*64 + ci)*65 + bp];
                float a0 = ap[0], a1 = ap[8], a2 = ap[16], a3 = ap[24];
                acc[0][0] += a0*bv.x; acc[0][1] += a0*bv.y; acc[0][2] += a0*bv.z; acc[0][3] += a0*bv.w;
                acc[1][0] += a1*bv.x; acc[1][1] += a1*bv.y; acc[1][2] += a1*bv.z; acc[1][3] += a1*bv.w;
                acc[2][0] += a2*bv.x; acc[2][1] += a2*bv.y; acc[2][2] += a2*bv.z; acc[2][3] += a2*bv.w;
                acc[3][0] += a3*bv.x; acc[3][1] += a3*bv.y; acc[3][2] += a3*bv.z; acc[3][3] += a3*bv.w;
            }
        }
    }
    // pool the thread's 4 cells (rows 0..3 at col ty) into the block's pool cell
    {
        float mx[4];
#pragma unroll
        for (int j = 0; j < 4; j++) mx[j] = -1e30f;
        bool any = false;
#pragma unroll
        for (int q = 0; q < 4; q++) {
            if (g_act3[(r0 + q)*S3 + (c0 + ty)]) {
                any = true;
#pragma unroll
                for (int j = 0; j < 4; j++) mx[j] = fmaxf(mx[j], acc[q][j]);
            }
        }
        if (any) {
#pragma unroll
            for (int j = 0; j < 4; j++) atomicMax(&se[co + j], encf(mx[j]));
        }
    }
    __syncthreads();
    {
        unsigned u = se[threadIdx.x];
        g_p4v[(blockIdx.y*S4 + blockIdx.x)*256 + threadIdx.x] = u ? eluf(decf(u)) : 0.f;
    }
}

// ---------------- K7: fc1 (20736 -> 32) + ELU ----------------
__global__ __launch_bounds__(256) void k_fc1(const float* __restrict__ w,
                                             const float* __restrict__ b) {
    int j = blockIdx.x;
    float s0 = 0.f, s1 = 0.f, s2 = 0.f, s3 = 0.f;
    for (int i = threadIdx.x; i < 20736; i += 1024) {
        int i0 = i, i1 = i + 256, i2 = i + 512, i3 = i + 768;
        { int c = i0/81, rem = i0 - c*81; s0 += g_p4v[rem*256 + c] * w[i0*32 + j]; }
        if (i1 < 20736) { int c = i1/81, rem = i1 - c*81; s1 += g_p4v[rem*256 + c] * w[i1*32 + j]; }
        if (i2 < 20736) { int c = i2/81, rem = i2 - c*81; s2 += g_p4v[rem*256 + c] * w[i2*32 + j]; }
        if (i3 < 20736) { int c = i3/81, rem = i3 - c*81; s3 += g_p4v[rem*256 + c] * w[i3*32 + j]; }
    }
    float s = (s0 + s1) + (s2 + s3);
    __shared__ float red[256];
    red[threadIdx.x] = s;
    __syncthreads();
    for (int o = 128; o > 0; o >>= 1) {
        if (threadIdx.x < o) red[threadIdx.x] += red[threadIdx.x + o];
        __syncthreads();
    }
    if (threadIdx.x == 0) {
        float z = red[0] + b[j];
        g_h[j] = z > 0.f ? z : expm1f(z);
    }
}

// ---------------- K8: fc2 (32 -> 5) + softmax ----------------
__global__ void k_fc2(const float* __restrict__ w, const float* __restrict__ b,
                      float* __restrict__ out) {
    if (threadIdx.x == 0) {
        float lg[5];
#pragma unroll
        for (int t = 0; t < 5; t++) lg[t] = b[t];
        for (int j = 0; j < 32; j++) {
            float h = g_h[j];
#pragma unroll
            for (int t = 0; t < 5; t++) lg[t] += h * w[j*5 + t];
        }
        float m = lg[0];
#pragma unroll
        for (int t = 1; t < 5; t++) m = fmaxf(m, lg[t]);
        float e[5], sum = 0.f;
#pragma unroll
        for (int t = 0; t < 5; t++) { e[t] = expf(lg[t] - m); sum += e[t]; }
        float inv = 1.f / sum;
#pragma unroll
        for (int t = 0; t < 5; t++) out[t] = e[t] * inv;
    }
}

// ---------------- K9: clear only the scattered cells ----------------
__global__ void k_clearpts(const int* __restrict__ coords, int P) {
    int p = blockIdx.x * blockDim.x + threadIdx.x;
    if (p >= P) return;
    g_x[coords[2*p]*S0 + coords[2*p+1]] = 0.f;
}

// ---------------- launch ----------------
extern "C" void kernel_launch(void* const* d_in, const int* in_sizes, int n_in,
                              void* d_out, int out_size) {
    const int*   coords = (const int*)  d_in[0];
    const float* feats  = (const float*)d_in[1];
    const float* w1     = (const float*)d_in[2];
    const float* w2     = (const float*)d_in[3];
    const float* w3     = (const float*)d_in[4];
    const float* w4     = (const float*)d_in[5];
    const float* fc1w   = (const float*)d_in[6];
    const float* fc1b   = (const float*)d_in[7];
    const float* fc2w   = (const float*)d_in[8];
    const float* fc2b   = (const float*)d_in[9];
    float* out = (float*)d_out;
    int P = in_sizes[1];

    cudaFuncSetAttribute(k_conv3, cudaFuncAttributeMaxDynamicSharedMemorySize, SMEM3_BYTES);
    cudaFuncSetAttribute(k_conv4, cudaFuncAttributeMaxDynamicSharedMemorySize, SMEM4_BYTES);

    k_scatter<<<(P + 255)/256, 256>>>(coords, feats, P);
    k_conv1<<<(P + 127)/128, 128>>>(coords, w1, P);
    k_decode0<<<S1*S1/256, 256>>>();
    k_conv2<<<(S1*S1 + 63)/64, 256>>>(w2);
    k_decode1<<<S2*S2*16/256, 256>>>();
    k_conv3<<<dim3(S2/8, S2/8), 256, SMEM3_BYTES>>>(w3);
    k_conv4<<<dim3(S3/4, S3/4), 256, SMEM4_BYTES>>>(w4);
    k_fc1<<<32, 256>>>(fc1w, fc1b);
    k_fc2<<<1, 32>>>(fc2w, fc2b, out);
    k_clearpts<<<(P + 255)/256, 256>>>(coords, P);
}

// round 14
// speedup vs baseline: 2.5556x; 1.1842x over previous
#include <cuda_runtime.h>
#include <math.h>

#define S0 3600
#define S1 720
#define S2 144
#define S3 36
#define S4 9

typedef unsigned long long u64;

// ---------------- static device scratch ----------------
__device__ __align__(16) float    g_x   [S0*S0];        // 51.8MB dense scattered input grid
__device__ __align__(16) unsigned g_p1e [S1*S1*10];     // encoded pool accumulators (level1)
__device__ __align__(16) float    g_p1v [S1*S1*10];     // decoded values (0 at inactive)
__device__ __align__(16) int      g_list[S1*S1];        // active cell list at level1
__device__ __align__(16) int      g_inv [S1*S1];        // cell -> list index
__device__ __align__(16) int      g_act1[S1*S1];        // level1 activity
__device__ int      g_cnt;
__device__ __align__(16) float    g_c2out[S1*S1*64];    // conv2 raw outputs by list idx
__device__ __align__(16) float    g_p2v [S2*S2*64];     // pooled level2 values
__device__ __align__(16) int      g_act2[S2*S2];
__device__ __align__(16) float    g_p3v [S3*S3*128];    // pooled level3 values
__device__ __align__(16) int      g_act3[S3*S3];
__device__ __align__(16) float    g_p4v [S4*S4*256];
__device__ float    g_h[32];

// ---------------- helpers ----------------
__device__ __forceinline__ unsigned encf(float f) {
    unsigned u = __float_as_uint(f);
    return (u & 0x80000000u) ? ~u : (u | 0x80000000u);
}
__device__ __forceinline__ float decf(unsigned u) {
    return __uint_as_float((u & 0x80000000u) ? (u & 0x7fffffffu) : ~u);
}
__device__ __forceinline__ float eluf(float x) {
    return x > 0.f ? x : expm1f(x);
}
// packed f32x2 FMA: d = a*b + d (independent lanes)
__device__ __forceinline__ void fma2(u64& d, u64 a, u64 b) {
    asm("fma.rn.f32x2 %0, %1, %2, %0;" : "+l"(d) : "l"(a), "l"(b));
}
__device__ __forceinline__ u64 pack2(float v) {
    u64 r;
    asm("mov.b64 %0, {%1, %1};" : "=l"(r) : "f"(v));
    return r;
}
__device__ __forceinline__ float2 unpack2(u64 a) {
    float2 r;
    asm("mov.b64 {%0, %1}, %2;" : "=f"(r.x), "=f"(r.y) : "l"(a));
    return r;
}

// ---------------- K0: scatter points onto grid ----------------
__global__ void k_scatter(const int* __restrict__ coords,
                          const float* __restrict__ feat, int P) {
    int p = blockIdx.x * blockDim.x + threadIdx.x;
    if (p >= P) return;
    int r = coords[2*p], c = coords[2*p+1];
    atomicAdd(&g_x[r*S0 + c], feat[p]);
}

// ---------------- K1: conv1 (1->10) at active sites, fused ELU + maxpool scatter ----------------
__global__ void k_conv1(const int* __restrict__ coords,
                        const float* __restrict__ w1, int P) {
    int p = blockIdx.x * blockDim.x + threadIdx.x;
    if (p >= P) return;
    int r = coords[2*p], c = coords[2*p+1];
    float acc[10];
#pragma unroll
    for (int co = 0; co < 10; co++) acc[co] = 0.f;
#pragma unroll
    for (int dr = -2; dr <= 2; dr++) {
        int rr = r + dr;
        if ((unsigned)rr >= (unsigned)S0) continue;
#pragma unroll
        for (int dc = -2; dc <= 2; dc++) {
            int cc = c + dc;
            if ((unsigned)cc >= (unsigned)S0) continue;
            float v = g_x[rr*S0 + cc];
            if (v != 0.f) {
                int tap = (dr+2)*5 + (dc+2);
#pragma unroll
                for (int co = 0; co < 10; co++) acc[co] += v * w1[tap*10 + co];
            }
        }
    }
    int pc = (r/5)*S1 + (c/5);
    unsigned* dst = &g_p1e[pc*10];
#pragma unroll
    for (int co = 0; co < 10; co++)
        atomicMax(&dst[co], encf(eluf(acc[co])));
}

// ---------------- K2: decode level1 + build list/inv/act + clear p1e ----------------
__global__ __launch_bounds__(256) void k_decode0() {
    int cell = blockIdx.x * blockDim.x + threadIdx.x;
    unsigned u0 = g_p1e[cell*10];
    bool act = (u0 != 0u);
    unsigned m = __ballot_sync(0xffffffffu, act);
    int idx = 0;
    if (m) {
        int lane = threadIdx.x & 31;
        int ldr  = __ffs(m) - 1;
        int base = 0;
        if (lane == ldr) base = atomicAdd(&g_cnt, __popc(m));
        base = __shfl_sync(0xffffffffu, base, ldr);
        idx = base + __popc(m & ((1u << lane) - 1u));
    }
    g_act1[cell] = act ? 1 : 0;
    if (act) { g_inv[cell] = idx; g_list[idx] = cell; }
#pragma unroll
    for (int j = 0; j < 10; j++) {
        unsigned u = g_p1e[cell*10 + j];
        g_p1v[cell*10 + j] = u ? decf(u) : 0.f;
        g_p1e[cell*10 + j] = 0u;
    }
}

// ---------------- K3: conv2 (10->64) GEMM-tiled, f32x2: 64 cells x 64 couts, thread 4x4 ----------------
__global__ __launch_bounds__(256) void k_conv2(const float* __restrict__ w2) {
    __shared__ float A_t[50*64];           // [kk][cell]
    __shared__ float w_s[50*64];           // [kk][co]
    __shared__ int   cs[64];
    __shared__ int   cv[64];
    int cnt  = g_cnt;
    int base = blockIdx.x * 64;
    if (base >= cnt) return;
    if (threadIdx.x < 64) {
        int idx = base + threadIdx.x;
        int ok  = idx < cnt;
        cs[threadIdx.x] = g_list[ok ? idx : base];
        cv[threadIdx.x] = ok;
    }
    int tx = threadIdx.x & 15;             // co = tx*4
    int ty = threadIdx.x >> 4;             // cells ty*4..+3
    u64 acc[4][2];
#pragma unroll
    for (int q = 0; q < 4; q++) { acc[q][0] = 0ull; acc[q][1] = 0ull; }

    for (int tr = 0; tr < 5; tr++) {       // K chunks of 50 (one tap-row)
        __syncthreads();
        {
            const float4* wp = (const float4*)(w2 + tr*50*64);
            for (int t = threadIdx.x; t < 50*64/4; t += 256)
                ((float4*)w_s)[t] = wp[t];
        }
        for (int t = threadIdx.x; t < 50*64; t += 256) {
            int cell = t & 63, kk = t >> 6;
            int tc = kk / 10, ci = kk - tc*10;
            int id = cs[cell];
            int rr = id / S1 + tr - 2;
            int cc = id % S1 + tc - 2;
            float v = 0.f;
            if ((unsigned)rr < (unsigned)S1 && (unsigned)cc < (unsigned)S1)
                v = g_p1v[(rr*S1 + cc)*10 + ci];
            A_t[kk*64 + cell] = v;
        }
        __syncthreads();
#pragma unroll 5
        for (int kk = 0; kk < 50; kk++) {
            float4 av = *(const float4*)&A_t[kk*64 + ty*4];
            ulonglong2 bq = *(const ulonglong2*)&w_s[kk*64 + tx*4];
            u64 p;
            p = pack2(av.x); fma2(acc[0][0], p, bq.x); fma2(acc[0][1], p, bq.y);
            p = pack2(av.y); fma2(acc[1][0], p, bq.x); fma2(acc[1][1], p, bq.y);
            p = pack2(av.z); fma2(acc[2][0], p, bq.x); fma2(acc[2][1], p, bq.y);
            p = pack2(av.w); fma2(acc[3][0], p, bq.x); fma2(acc[3][1], p, bq.y);
        }
    }
#pragma unroll
    for (int q = 0; q < 4; q++) {
        int cell = ty*4 + q;
        if (cv[cell]) {
            float2 f0 = unpack2(acc[q][0]);
            float2 f1 = unpack2(acc[q][1]);
            *(float4*)&g_c2out[(base + cell)*64 + tx*4] =
                make_float4(f0.x, f0.y, f1.x, f1.y);
        }
    }
}

// ---------------- K4: gather-pool 5x5 level1->level2 + ELU + act2 (+ reset cnt) ----------------
__global__ __launch_bounds__(256) void k_decode1() {
    int t = blockIdx.x * blockDim.x + threadIdx.x;
    int cell = t >> 4, cg = t & 15;
    int r2 = cell / S2, c2 = cell - r2*S2;
    float m0 = -1e30f, m1 = -1e30f, m2 = -1e30f, m3 = -1e30f;
    bool any = false;
#pragma unroll
    for (int dr = 0; dr < 5; dr++) {
#pragma unroll
        for (int dc = 0; dc < 5; dc++) {
            int cid = (r2*5 + dr)*S1 + (c2*5 + dc);
            if (g_act1[cid]) {
                any = true;
                const float4 v = *(const float4*)&g_c2out[g_inv[cid]*64 + cg*4];
                m0 = fmaxf(m0, v.x); m1 = fmaxf(m1, v.y);
                m2 = fmaxf(m2, v.z); m3 = fmaxf(m3, v.w);
            }
        }
    }
    float4 o;
    if (any) o = make_float4(eluf(m0), eluf(m1), eluf(m2), eluf(m3));
    else     o = make_float4(0.f, 0.f, 0.f, 0.f);
    *(float4*)&g_p2v[cell*64 + cg*4] = o;
    if (cg == 0) g_act2[cell] = any ? 1 : 0;
    if (t == 0) g_cnt = 0;
}

// ---------------- K5: conv3 (64->128) GEMM-tiled, f32x2, vectorized a-loads, in-block pool ----------------
// in_p [pos][ci] stride 68 (16B-aligned); thread = 4 rows x 1 col x 8 couts = 1 pool cell
#define SMEM3_BYTES ((144*68 + 64*128)*4 + 512*4)
__global__ __launch_bounds__(256) void k_conv3(const float* __restrict__ w3) {
    extern __shared__ float smem3[];
    float*    in_p = smem3;                        // [144 pos][68]
    float*    w_s  = smem3 + 144*68;               // [64 ci][128 co]
    unsigned* se   = (unsigned*)(w_s + 64*128);    // [4 pool][128 co]
    int r0 = blockIdx.y * 8, c0 = blockIdx.x * 8;
    for (int t = threadIdx.x; t < 144*64; t += 256) {
        int ci = t & 63, pos = t >> 6;
        int wr = pos / 12, wc = pos - wr*12;
        int gr = r0 - 2 + wr, gc = c0 - 2 + wc;
        float v = 0.f;
        if ((unsigned)gr < (unsigned)S2 && (unsigned)gc < (unsigned)S2)
            v = g_p2v[(gr*S2 + gc)*64 + ci];
        in_p[pos*68 + ci] = v;
    }
    se[threadIdx.x] = 0u; se[threadIdx.x + 256] = 0u;
    int tx = threadIdx.x & 15;             // co = tx*8
    int ty = threadIdx.x >> 4;
    int rh = ty >> 3, cf = ty & 7;         // rows rh*4..+3, col cf
    int co = tx*8;
    u64 acc[4][4];
#pragma unroll
    for (int q = 0; q < 4; q++)
#pragma unroll
        for (int j = 0; j < 4; j++) acc[q][j] = 0ull;

    for (int tap = 0; tap < 25; tap++) {
        __syncthreads();
        {
            const float4* wp = (const float4*)(w3 + (size_t)tap*64*128);
            for (int t = threadIdx.x; t < 64*128/4; t += 256)
                ((float4*)w_s)[t] = wp[t];
        }
        __syncthreads();
        int tr = tap / 5, tc = tap - tr*5;
        int p0 = (rh*4 + tr)*12 + cf + tc;
#pragma unroll 2
        for (int c4 = 0; c4 < 16; c4++) {
            float av[4][4];
            *(float4*)av[0] = *(const float4*)&in_p[p0*68       + c4*4];
            *(float4*)av[1] = *(const float4*)&in_p[(p0+12)*68  + c4*4];
            *(float4*)av[2] = *(const float4*)&in_p[(p0+24)*68  + c4*4];
            *(float4*)av[3] = *(const float4*)&in_p[(p0+36)*68  + c4*4];
#pragma unroll
            for (int e = 0; e < 4; e++) {
                ulonglong2 b0 = *(const ulonglong2*)&w_s[(c4*4+e)*128 + co];
                ulonglong2 b1 = *(const ulonglong2*)&w_s[(c4*4+e)*128 + co + 4];
                u64 p;
                p = pack2(av[0][e]); fma2(acc[0][0],p,b0.x); fma2(acc[0][1],p,b0.y); fma2(acc[0][2],p,b1.x); fma2(acc[0][3],p,b1.y);
                p = pack2(av[1][e]); fma2(acc[1][0],p,b0.x); fma2(acc[1][1],p,b0.y); fma2(acc[1][2],p,b1.x); fma2(acc[1][3],p,b1.y);
                p = pack2(av[2][e]); fma2(acc[2][0],p,b0.x); fma2(acc[2][1],p,b0.y); fma2(acc[2][2],p,b1.x); fma2(acc[2][3],p,b1.y);
                p = pack2(av[3][e]); fma2(acc[3][0],p,b0.x); fma2(acc[3][1],p,b0.y); fma2(acc[3][2],p,b1.x); fma2(acc[3][3],p,b1.y);
            }
        }
    }
    // thread's 4 cells pool into one level-3 cell
    {
        float mx[8];
#pragma unroll
        for (int j = 0; j < 8; j++) mx[j] = -1e30f;
        bool any = false;
#pragma unroll
        for (int q = 0; q < 4; q++) {
            int gr = r0 + rh*4 + q, gc = c0 + cf;
            if (g_act2[gr*S2 + gc]) {
                any = true;
#pragma unroll
                for (int j = 0; j < 4; j++) {
                    float2 f = unpack2(acc[q][j]);
                    mx[2*j]   = fmaxf(mx[2*j],   f.x);
                    mx[2*j+1] = fmaxf(mx[2*j+1], f.y);
                }
            }
        }
        if (any) {
            int pp = rh*2 + (cf >> 2);
            unsigned* d = &se[pp*128 + co];
#pragma unroll
            for (int j = 0; j < 8; j++) atomicMax(d + j, encf(mx[j]));
        }
    }
    __syncthreads();
    for (int e = threadIdx.x; e < 512; e += 256) {
        unsigned u = se[e];
        int pp = e >> 7, ch = e & 127;
        int pr = (r0 >> 2) + (pp >> 1), pc = (c0 >> 2) + (pp & 1);
        g_p3v[(pr*S3 + pc)*128 + ch] = u ? eluf(decf(u)) : 0.f;
        if (ch == 0) g_act3[pr*S3 + pc] = (u != 0u) ? 1 : 0;
    }
}

// ---------------- K6: conv4 (128->256) f32x2, co-split x2; block = one pool cell, half the couts ----------------
// 256 threads: tx (0..31) co=tx*4 within 128-half; ty (0..7) -> cells 2ty, 2ty+1
#define SMEM4_BYTES ((64*132 + 64*128)*4 + 128*4)
__global__ __launch_bounds__(256) void k_conv4(const float* __restrict__ w4) {
    extern __shared__ float smem4[];
    float*    in_p = smem4;                        // [64 pos][132]
    float*    w_s  = smem4 + 64*132;               // [64 ci][128 co-half]
    unsigned* se   = (unsigned*)(w_s + 64*128);    // [128 co-half]
    int r0 = blockIdx.y * 4, c0 = blockIdx.x * 4;
    int h  = blockIdx.z;                           // cout half
    for (int t = threadIdx.x; t < 64*128; t += 256) {
        int ci = t & 127, pos = t >> 7;
        int wr = pos >> 3, wc = pos & 7;
        int gr = r0 - 2 + wr, gc = c0 - 2 + wc;
        float v = 0.f;
        if ((unsigned)gr < (unsigned)S3 && (unsigned)gc < (unsigned)S3)
            v = g_p3v[(gr*S3 + gc)*128 + ci];
        in_p[pos*132 + ci] = v;
    }
    if (threadIdx.x < 128) se[threadIdx.x] = 0u;
    int tx = threadIdx.x & 31;             // co = tx*4 (within half)
    int ty = threadIdx.x >> 5;             // cell pair: cells 2ty, 2ty+1
    int co = tx*4;
    int ca = 2*ty, cb = 2*ty + 1;
    int ra = ca >> 2, caq = ca & 3;
    int rb = cb >> 2, cbq = cb & 3;
    u64 acc[2][2];
    acc[0][0]=0ull; acc[0][1]=0ull; acc[1][0]=0ull; acc[1][1]=0ull;

    for (int tap = 0; tap < 25; tap++) {
        int tr = tap / 5, tc = tap - tr*5;
        for (int cic = 0; cic < 2; cic++) {
            __syncthreads();
            // stage weight chunk [64 ci][128 co-half]
            for (int t = threadIdx.x; t < 64*32; t += 256) {
                int ci = t >> 5, c4 = t & 31;
                ((float4*)w_s)[ci*32 + c4] =
                    *(const float4*)(w4 + ((size_t)(tap*128 + cic*64 + ci))*256 + h*128 + c4*4);
            }
            __syncthreads();
            int pa = (ra + tr)*8 + caq + tc;
            int pb = (rb + tr)*8 + cbq + tc;
#pragma unroll 4
            for (int c4 = 0; c4 < 16; c4++) {
                float aa[4], ab[4];
                *(float4*)aa = *(const float4*)&in_p[pa*132 + cic*64 + c4*4];
                *(float4*)ab = *(const float4*)&in_p[pb*132 + cic*64 + c4*4];
#pragma unroll
                for (int e = 0; e < 4; e++) {
                    ulonglong2 bq = *(const ulonglong2*)&w_s[(c4*4+e)*128 + co];
                    u64 p;
                    p = pack2(aa[e]); fma2(acc[0][0], p, bq.x); fma2(acc[0][1], p, bq.y);
                    p = pack2(ab[e]); fma2(acc[1][0], p, bq.x); fma2(acc[1][1], p, bq.y);
                }
            }
        }
    }
    // pool thread's 2 cells into the block's pool cell
    {
        float mx[4] = {-1e30f, -1e30f, -1e30f, -1e30f};
        bool any = false;
        int cells[2] = {ca, cb};
#pragma unroll
        for (int q = 0; q < 2; q++) {
            int cc = cells[q];
            if (g_act3[(r0 + (cc >> 2))*S3 + (c0 + (cc & 3))]) {
                any = true;
                float2 f0 = unpack2(acc[q][0]);
                float2 f1 = unpack2(acc[q][1]);
                mx[0] = fmaxf(mx[0], f0.x); mx[1] = fmaxf(mx[1], f0.y);
                mx[2] = fmaxf(mx[2], f1.x); mx[3] = fmaxf(mx[3], f1.y);
            }
        }
        if (any) {
#pragma unroll
            for (int j = 0; j < 4; j++) atomicMax(&se[co + j], encf(mx[j]));
        }
    }
    __syncthreads();
    if (threadIdx.x < 128) {
        unsigned u = se[threadIdx.x];
        g_p4v[(blockIdx.y*S4 + blockIdx.x)*256 + h*128 + threadIdx.x] = u ? eluf(decf(u)) : 0.f;
    }
}

// ---------------- K7: fc1 (20736 -> 32) + ELU ----------------
__global__ __launch_bounds__(256) void k_fc1(const float* __restrict__ w,
                                             const float* __restrict__ b) {
    int j = blockIdx.x;
    float s0 = 0.f, s1 = 0.f, s2 = 0.f, s3 = 0.f;
    for (int i = threadIdx.x; i < 20736; i += 1024) {
        int i0 = i, i1 = i + 256, i2 = i + 512, i3 = i + 768;
        { int c = i0/81, rem = i0 - c*81; s0 += g_p4v[rem*256 + c] * w[i0*32 + j]; }
        if (i1 < 20736) { int c = i1/81, rem = i1 - c*81; s1 += g_p4v[rem*256 + c] * w[i1*32 + j]; }
        if (i2 < 20736) { int c = i2/81, rem = i2 - c*81; s2 += g_p4v[rem*256 + c] * w[i2*32 + j]; }
        if (i3 < 20736) { int c = i3/81, rem = i3 - c*81; s3 += g_p4v[rem*256 + c] * w[i3*32 + j]; }
    }
    float s = (s0 + s1) + (s2 + s3);
    __shared__ float red[256];
    red[threadIdx.x] = s;
    __syncthreads();
    for (int o = 128; o > 0; o >>= 1) {
        if (threadIdx.x < o) red[threadIdx.x] += red[threadIdx.x + o];
        __syncthreads();
    }
    if (threadIdx.x == 0) {
        float z = red[0] + b[j];
        g_h[j] = z > 0.f ? z : expm1f(z);
    }
}

// ---------------- K8: fc2 (32 -> 5) + softmax ----------------
__global__ void k_fc2(const float* __restrict__ w, const float* __restrict__ b,
                      float* __restrict__ out) {
    if (threadIdx.x == 0) {
        float lg[5];
#pragma unroll
        for (int t = 0; t < 5; t++) lg[t] = b[t];
        for (int j = 0; j < 32; j++) {
            float h = g_h[j];
#pragma unroll
            for (int t = 0; t < 5; t++) lg[t] += h * w[j*5 + t];
        }
        float m = lg[0];
#pragma unroll
        for (int t = 1; t < 5; t++) m = fmaxf(m, lg[t]);
        float e[5], sum = 0.f;
#pragma unroll
        for (int t = 0; t < 5; t++) { e[t] = expf(lg[t] - m); sum += e[t]; }
        float inv = 1.f / sum;
#pragma unroll
        for (int t = 0; t < 5; t++) out[t] = e[t] * inv;
    }
}

// ---------------- K9: clear only the scattered cells ----------------
__global__ void k_clearpts(const int* __restrict__ coords, int P) {
    int p = blockIdx.x * blockDim.x + threadIdx.x;
    if (p >= P) return;
    g_x[coords[2*p]*S0 + coords[2*p+1]] = 0.f;
}

// ---------------- launch ----------------
extern "C" void kernel_launch(void* const* d_in, const int* in_sizes, int n_in,
                              void* d_out, int out_size) {
    const int*   coords = (const int*)  d_in[0];
    const float* feats  = (const float*)d_in[1];
    const float* w1     = (const float*)d_in[2];
    const float* w2     = (const float*)d_in[3];
    const float* w3     = (const float*)d_in[4];
    const float* w4     = (const float*)d_in[5];
    const float* fc1w   = (const float*)d_in[6];
    const float* fc1b   = (const float*)d_in[7];
    const float* fc2w   = (const float*)d_in[8];
    const float* fc2b   = (const float*)d_in[9];
    float* out = (float*)d_out;
    int P = in_sizes[1];

    cudaFuncSetAttribute(k_conv3, cudaFuncAttributeMaxDynamicSharedMemorySize, SMEM3_BYTES);
    cudaFuncSetAttribute(k_conv4, cudaFuncAttributeMaxDynamicSharedMemorySize, SMEM4_BYTES);

    k_scatter<<<(P + 255)/256, 256>>>(coords, feats, P);
    k_conv1<<<(P + 127)/128, 128>>>(coords, w1, P);
    k_decode0<<<S1*S1/256, 256>>>();
    k_conv2<<<(S1*S1 + 63)/64, 256>>>(w2);                      // profiled slot
    k_decode1<<<S2*S2*16/256, 256>>>();
    k_conv3<<<dim3(S2/8, S2/8), 256, SMEM3_BYTES>>>(w3);
    k_conv4<<<dim3(S3/4, S3/4, 2), 256, SMEM4_BYTES>>>(w4);
    k_fc1<<<32, 256>>>(fc1w, fc1b);
    k_fc2<<<1, 32>>>(fc2w, fc2b, out);
    k_clearpts<<<(P + 255)/256, 256>>>(coords, P);
}